// round 1
// baseline (speedup 1.0000x reference)
#include <cuda_runtime.h>
#include <cstdint>

#define Vn   20000
#define NNZn 640000
#define Bn   16
#define CINn 128
#define COUTn 128
#define Rn   4
#define Fn   2048   // Bn * CINn

// ---------------- scratch (static device memory; no allocation at runtime) ----------------
__device__ float g_xs[(size_t)Rn * Vn * Fn];   // 4 Chebyshev terms, each (V, 2048)  (~655 MB)
__device__ int   g_rowptr[Vn + 1];
__device__ int   g_cnt[Vn];
__device__ int   g_fill[Vn];
__device__ int   g_cols[NNZn];
__device__ float g_vals[NNZn];

// ---------------- CSR build ----------------
__global__ void zero_kernel() {
    int i = blockIdx.x * blockDim.x + threadIdx.x;
    if (i < Vn) { g_cnt[i] = 0; g_fill[i] = 0; }
}

__global__ void count_kernel(const int* __restrict__ rows) {
    int j = blockIdx.x * blockDim.x + threadIdx.x;
    if (j < NNZn) atomicAdd(&g_cnt[rows[j]], 1);
}

// single-block exclusive scan over 20000 counters
__global__ void scan_kernel() {
    __shared__ int s[1024];
    int tid = threadIdx.x;
    int carry = 0;
    for (int base = 0; base < Vn; base += 1024) {
        int i = base + tid;
        int v = (i < Vn) ? g_cnt[i] : 0;
        s[tid] = v;
        __syncthreads();
        for (int off = 1; off < 1024; off <<= 1) {
            int t = (tid >= off) ? s[tid - off] : 0;
            __syncthreads();
            s[tid] += t;
            __syncthreads();
        }
        if (i < Vn) g_rowptr[i] = carry + s[tid] - v;
        carry += s[1023];
        __syncthreads();
    }
    if (tid == 0) g_rowptr[Vn] = carry;
}

__global__ void scatter_kernel(const int* __restrict__ rows,
                               const int* __restrict__ cols,
                               const float* __restrict__ vals) {
    int j = blockIdx.x * blockDim.x + threadIdx.x;
    if (j < NNZn) {
        int r = rows[j];
        int p = g_rowptr[r] + atomicAdd(&g_fill[r], 1);
        g_cols[p] = cols[j];
        g_vals[p] = vals[j];
    }
}

// ---------------- transpose x (B,Cin,V) -> x0 (V, 2048) ----------------
__global__ void transpose_kernel(const float* __restrict__ x) {
    __shared__ float tile[32][33];
    int v0 = blockIdx.x * 32;
    int c0 = blockIdx.y * 32;
    int tx = threadIdx.x, ty = threadIdx.y;
    tile[ty][tx] = x[(size_t)(c0 + ty) * Vn + (v0 + tx)];
    __syncthreads();
    g_xs[(size_t)(v0 + ty) * Fn + (c0 + tx)] = tile[tx][ty];
}

// ---------------- SpMM (CSR gather), feature-quartered for L2 residency ----------------
// grid: (Vn, 4), block: 128 threads, each thread one float4 (512 floats/block)
template <int MODE>  // 0: xk = L*y ; 1: xk = 2*L*y - xm2
__global__ void __launch_bounds__(128) spmm_kernel(int iy, int im2, int io) {
    const size_t term = (size_t)Vn * Fn;
    const float4* __restrict__ y4 = reinterpret_cast<const float4*>(g_xs + (size_t)iy  * term);
    const float4* __restrict__ m4 = reinterpret_cast<const float4*>(g_xs + (size_t)im2 * term);
    float4* __restrict__       o4 = reinterpret_cast<float4*>(g_xs + (size_t)io * term);

    int v = blockIdx.x;
    int f = blockIdx.y * 128 + threadIdx.x;   // float4 index 0..511 within the row
    int s = g_rowptr[v], e = g_rowptr[v + 1];

    float4 acc0 = make_float4(0.f, 0.f, 0.f, 0.f);
    float4 acc1 = make_float4(0.f, 0.f, 0.f, 0.f);

    int j = s;
    for (; j + 1 < e; j += 2) {
        float w0 = __ldg(&g_vals[j]);     int c0 = __ldg(&g_cols[j]);
        float w1 = __ldg(&g_vals[j + 1]); int c1 = __ldg(&g_cols[j + 1]);
        float4 r0 = y4[(size_t)c0 * 512 + f];
        float4 r1 = y4[(size_t)c1 * 512 + f];
        acc0.x = fmaf(w0, r0.x, acc0.x); acc0.y = fmaf(w0, r0.y, acc0.y);
        acc0.z = fmaf(w0, r0.z, acc0.z); acc0.w = fmaf(w0, r0.w, acc0.w);
        acc1.x = fmaf(w1, r1.x, acc1.x); acc1.y = fmaf(w1, r1.y, acc1.y);
        acc1.z = fmaf(w1, r1.z, acc1.z); acc1.w = fmaf(w1, r1.w, acc1.w);
    }
    if (j < e) {
        float w0 = __ldg(&g_vals[j]); int c0 = __ldg(&g_cols[j]);
        float4 r0 = y4[(size_t)c0 * 512 + f];
        acc0.x = fmaf(w0, r0.x, acc0.x); acc0.y = fmaf(w0, r0.y, acc0.y);
        acc0.z = fmaf(w0, r0.z, acc0.z); acc0.w = fmaf(w0, r0.w, acc0.w);
    }
    float4 res;
    res.x = acc0.x + acc1.x; res.y = acc0.y + acc1.y;
    res.z = acc0.z + acc1.z; res.w = acc0.w + acc1.w;

    size_t oi = (size_t)v * 512 + f;
    if (MODE == 0) {
        __stcs(&o4[oi], res);
    } else {
        float4 m = __ldcs(&m4[oi]);
        res.x = 2.f * res.x - m.x; res.y = 2.f * res.y - m.y;
        res.z = 2.f * res.z - m.z; res.w = 2.f * res.w - m.w;
        __stcs(&o4[oi], res);
    }
}

// ---------------- fused GEMM over all 4 terms: out(b,o,v) = sum_{r,i} xs[r][v][b*128+i] * W[r][i][o] + bias[o]
__device__ __forceinline__ unsigned f2tf(float f) {
    unsigned u;
    asm("cvt.rna.tf32.f32 %0, %1;" : "=r"(u) : "f"(f));
    return u;
}

#define MMA_TF32(C, A, Bf)                                                                  \
    asm volatile("mma.sync.aligned.m16n8k8.row.col.f32.tf32.tf32.f32 "                     \
                 "{%0,%1,%2,%3},{%4,%5,%6,%7},{%8,%9},{%0,%1,%2,%3};"                       \
                 : "+f"((C)[0]), "+f"((C)[1]), "+f"((C)[2]), "+f"((C)[3])                   \
                 : "r"((A)[0]), "r"((A)[1]), "r"((A)[2]), "r"((A)[3]),                      \
                   "r"((Bf)[0]), "r"((Bf)[1]))

// block tile: M=64 (v), N=128 (o), K=512 in chunks of 32. 256 threads = 8 warps (2 x 4).
__global__ void __launch_bounds__(256) gemm_kernel(const float* __restrict__ weight,
                                                   const float* __restrict__ bias,
                                                   float* __restrict__ out) {
    __shared__ unsigned smem[8320];                 // 33.3 KB pool
    unsigned* As = smem;                            // [64][36]  (2304)
    unsigned* Ws = smem + 2304;                     // [32][132] (4224)
    float*    Cs = reinterpret_cast<float*>(smem);  // [128][65] (aliased after compute)

    int tid  = threadIdx.x;
    int lane = tid & 31;
    int warp = tid >> 5;
    int wm   = warp & 1;   // 0..1 : 32 v-rows each
    int wn   = warp >> 1;  // 0..3 : 32 o-cols each
    int bb   = blockIdx.y;
    int v0   = blockIdx.x * 64;

    float c[2][4][4];
#pragma unroll
    for (int nt = 0; nt < 4; nt++) {
        int o = wn * 32 + nt * 8 + (lane & 3) * 2;
        float b0 = bias[o], b1 = bias[o + 1];
#pragma unroll
        for (int mt = 0; mt < 2; mt++) {
            c[mt][nt][0] = b0; c[mt][nt][1] = b1;
            c[mt][nt][2] = b0; c[mt][nt][3] = b1;
        }
    }

    for (int k0 = 0; k0 < 512; k0 += 32) {
        int r  = k0 >> 7;
        int i0 = k0 & 127;
        // load A tile: 64 rows x 32 floats (256B contiguous per row)
        {
            int rowh = tid >> 3;
            int c4   = (tid & 7) * 4;
#pragma unroll
            for (int p = 0; p < 2; p++) {
                int row = p * 32 + rowh;
                int v   = v0 + row;
                float4 val = make_float4(0.f, 0.f, 0.f, 0.f);
                if (v < Vn)
                    val = *reinterpret_cast<const float4*>(
                        g_xs + (size_t)(r * Vn + v) * Fn + bb * 128 + i0 + c4);
                unsigned* dst = As + row * 36 + c4;
                dst[0] = f2tf(val.x); dst[1] = f2tf(val.y);
                dst[2] = f2tf(val.z); dst[3] = f2tf(val.w);
            }
        }
        // load W tile: 32 x 128 (weight is already (512,128) row-major = (R,Cin,Cout))
        {
#pragma unroll
            for (int idx = tid; idx < 1024; idx += 256) {
                int kk = idx >> 5;
                int oc = (idx & 31) * 4;
                float4 w = *reinterpret_cast<const float4*>(
                    weight + (size_t)(k0 + kk) * 128 + oc);
                unsigned* dst = Ws + kk * 132 + oc;
                dst[0] = f2tf(w.x); dst[1] = f2tf(w.y);
                dst[2] = f2tf(w.z); dst[3] = f2tf(w.w);
            }
        }
        __syncthreads();

#pragma unroll
        for (int k8 = 0; k8 < 32; k8 += 8) {
            unsigned a[2][4];
            int kq = k8 + (lane & 3);
#pragma unroll
            for (int mt = 0; mt < 2; mt++) {
                int arow = wm * 32 + mt * 16 + (lane >> 2);
                a[mt][0] = As[arow * 36 + kq];
                a[mt][1] = As[(arow + 8) * 36 + kq];
                a[mt][2] = As[arow * 36 + kq + 4];
                a[mt][3] = As[(arow + 8) * 36 + kq + 4];
            }
            unsigned bf[4][2];
#pragma unroll
            for (int nt = 0; nt < 4; nt++) {
                int o = wn * 32 + nt * 8 + (lane >> 2);
                bf[nt][0] = Ws[kq * 132 + o];
                bf[nt][1] = Ws[(kq + 4) * 132 + o];
            }
#pragma unroll
            for (int mt = 0; mt < 2; mt++)
#pragma unroll
                for (int nt = 0; nt < 4; nt++)
                    MMA_TF32(c[mt][nt], a[mt], bf[nt]);
        }
        __syncthreads();
    }

    // stage C into shared as [o][v] for coalesced (B,Cout,V) stores
#pragma unroll
    for (int mt = 0; mt < 2; mt++)
#pragma unroll
        for (int nt = 0; nt < 4; nt++) {
            int vr = wm * 32 + mt * 16 + (lane >> 2);
            int o  = wn * 32 + nt * 8 + (lane & 3) * 2;
            Cs[o * 65 + vr]           = c[mt][nt][0];
            Cs[(o + 1) * 65 + vr]     = c[mt][nt][1];
            Cs[o * 65 + vr + 8]       = c[mt][nt][2];
            Cs[(o + 1) * 65 + vr + 8] = c[mt][nt][3];
        }
    __syncthreads();

    for (int idx = tid; idx < 128 * 64; idx += 256) {
        int o  = idx >> 6;
        int vl = idx & 63;
        int v  = v0 + vl;
        if (v < Vn)
            out[((size_t)bb * 128 + o) * Vn + v] = Cs[o * 65 + vl];
    }
}

// ---------------- launch ----------------
extern "C" void kernel_launch(void* const* d_in, const int* in_sizes, int n_in,
                              void* d_out, int out_size) {
    const float* x        = (const float*)d_in[0];
    const float* weight   = (const float*)d_in[1];
    const float* bias     = (const float*)d_in[2];
    const float* lap_vals = (const float*)d_in[3];
    const int*   lap_rows = (const int*)d_in[4];
    const int*   lap_cols = (const int*)d_in[5];
    float* out = (float*)d_out;

    // CSR build
    zero_kernel<<<(Vn + 255) / 256, 256>>>();
    count_kernel<<<NNZn / 256, 256>>>(lap_rows);
    scan_kernel<<<1, 1024>>>();
    scatter_kernel<<<NNZn / 256, 256>>>(lap_rows, lap_cols, lap_vals);

    // x0 = transpose(x) into g_xs[0]
    transpose_kernel<<<dim3(Vn / 32, Fn / 32), dim3(32, 32)>>>(x);

    // Chebyshev recursion: x1 = L x0 ; x2 = 2 L x1 - x0 ; x3 = 2 L x2 - x1
    spmm_kernel<0><<<dim3(Vn, 4), 128>>>(0, 0, 1);
    spmm_kernel<1><<<dim3(Vn, 4), 128>>>(1, 0, 2);
    spmm_kernel<1><<<dim3(Vn, 4), 128>>>(2, 1, 3);

    // fused GEMM over all 4 terms + bias, writes (B, Cout, V)
    gemm_kernel<<<dim3((Vn + 63) / 64, Bn), 256>>>(weight, bias, out);
}

// round 2
// speedup vs baseline: 1.2732x; 1.2732x over previous
#include <cuda_runtime.h>
#include <cuda_fp16.h>
#include <cstdint>

#define Vn   20000
#define NNZn 640000
#define Bn   16
#define CINn 128
#define COUTn 128
#define Rn   4
#define Fn   2048   // Bn * CINn

// ---------------- scratch (static device memory; no allocation at runtime) ----------------
__device__ __half g_xh[(size_t)Rn * Vn * Fn];   // 4 Chebyshev terms, each (V, 2048) fp16 (~327 MB)
__device__ int    g_rowptr[Vn + 1];
__device__ int    g_cnt[Vn];
__device__ int    g_fill[Vn];
__device__ int    g_cols[NNZn];
__device__ float  g_vals[NNZn];

// ---------------- CSR build ----------------
__global__ void zero_kernel() {
    int i = blockIdx.x * blockDim.x + threadIdx.x;
    if (i < Vn) { g_cnt[i] = 0; g_fill[i] = 0; }
}

__global__ void count_kernel(const int* __restrict__ rows) {
    int j = blockIdx.x * blockDim.x + threadIdx.x;
    if (j < NNZn) atomicAdd(&g_cnt[rows[j]], 1);
}

// single-block exclusive scan over 20000 counters
__global__ void scan_kernel() {
    __shared__ int s[1024];
    int tid = threadIdx.x;
    int carry = 0;
    for (int base = 0; base < Vn; base += 1024) {
        int i = base + tid;
        int v = (i < Vn) ? g_cnt[i] : 0;
        s[tid] = v;
        __syncthreads();
        for (int off = 1; off < 1024; off <<= 1) {
            int t = (tid >= off) ? s[tid - off] : 0;
            __syncthreads();
            s[tid] += t;
            __syncthreads();
        }
        if (i < Vn) g_rowptr[i] = carry + s[tid] - v;
        carry += s[1023];
        __syncthreads();
    }
    if (tid == 0) g_rowptr[Vn] = carry;
}

__global__ void scatter_kernel(const int* __restrict__ rows,
                               const int* __restrict__ cols,
                               const float* __restrict__ vals) {
    int j = blockIdx.x * blockDim.x + threadIdx.x;
    if (j < NNZn) {
        int r = rows[j];
        int p = g_rowptr[r] + atomicAdd(&g_fill[r], 1);
        g_cols[p] = cols[j];
        g_vals[p] = vals[j];
    }
}

// ---------------- transpose x (B,Cin,V) -> x0 (V, 2048) fp16 ----------------
__global__ void transpose_kernel(const float* __restrict__ x) {
    __shared__ float tile[32][33];
    int v0 = blockIdx.x * 32;
    int c0 = blockIdx.y * 32;
    int tx = threadIdx.x, ty = threadIdx.y;
    tile[ty][tx] = x[(size_t)(c0 + ty) * Vn + (v0 + tx)];
    __syncthreads();
    g_xh[(size_t)(v0 + ty) * Fn + (c0 + tx)] = __float2half_rn(tile[tx][ty]);
}

// ---------------- SpMM (CSR gather), fp16 rows, feature-halved for L2 residency ----------------
// grid: (Vn, 2), block: 128 threads, each thread one uint4 = 8 halves (1024 halves/block)
template <int MODE>  // 0: xk = L*y ; 1: xk = 2*L*y - xm2
__global__ void __launch_bounds__(128) spmm_kernel(int iy, int im2, int io) {
    const size_t term = (size_t)Vn * Fn;
    const uint4* __restrict__ y4 = reinterpret_cast<const uint4*>(g_xh + (size_t)iy  * term);
    const float4* __restrict__ m4 = reinterpret_cast<const float4*>(g_xh + (size_t)im2 * term);
    float4* __restrict__       o4 = reinterpret_cast<float4*>(g_xh + (size_t)io * term);

    int v = blockIdx.x;
    int f = blockIdx.y * 128 + threadIdx.x;   // uint4 index 0..255 within the row
    int s = g_rowptr[v], e = g_rowptr[v + 1];

    float acc[8];
#pragma unroll
    for (int q = 0; q < 8; q++) acc[q] = 0.f;

    int j = s;
    for (; j + 1 < e; j += 2) {
        float w0 = __ldg(&g_vals[j]);     int c0 = __ldg(&g_cols[j]);
        float w1 = __ldg(&g_vals[j + 1]); int c1 = __ldg(&g_cols[j + 1]);
        uint4 r0 = y4[(size_t)c0 * 256 + f];
        uint4 r1 = y4[(size_t)c1 * 256 + f];
        const __half2* h0 = reinterpret_cast<const __half2*>(&r0);
        const __half2* h1 = reinterpret_cast<const __half2*>(&r1);
#pragma unroll
        for (int q = 0; q < 4; q++) {
            float2 a = __half22float2(h0[q]);
            float2 b = __half22float2(h1[q]);
            acc[2 * q]     = fmaf(w0, a.x, acc[2 * q]);
            acc[2 * q + 1] = fmaf(w0, a.y, acc[2 * q + 1]);
            acc[2 * q]     = fmaf(w1, b.x, acc[2 * q]);
            acc[2 * q + 1] = fmaf(w1, b.y, acc[2 * q + 1]);
        }
    }
    if (j < e) {
        float w0 = __ldg(&g_vals[j]); int c0 = __ldg(&g_cols[j]);
        uint4 r0 = y4[(size_t)c0 * 256 + f];
        const __half2* h0 = reinterpret_cast<const __half2*>(&r0);
#pragma unroll
        for (int q = 0; q < 4; q++) {
            float2 a = __half22float2(h0[q]);
            acc[2 * q]     = fmaf(w0, a.x, acc[2 * q]);
            acc[2 * q + 1] = fmaf(w0, a.y, acc[2 * q + 1]);
        }
    }

    size_t oi2 = (size_t)v * 128 + (f >> 1);      // float4 index (8 halves = 16B... see below)
    // we address output as float4 = 8 bytes? No: pack 8 halves = 16B = one uint4/float4.
    size_t oi = (size_t)v * 256 + f;              // in uint4 units; o4 is float4* (16B) -> same index
    if (MODE == 1) {
        float4 mraw = __ldcs(&m4[oi]);
        const __half2* mh = reinterpret_cast<const __half2*>(&mraw);
#pragma unroll
        for (int q = 0; q < 4; q++) {
            float2 m = __half22float2(mh[q]);
            acc[2 * q]     = 2.f * acc[2 * q]     - m.x;
            acc[2 * q + 1] = 2.f * acc[2 * q + 1] - m.y;
        }
    }
    float4 outv;
    __half2* oh = reinterpret_cast<__half2*>(&outv);
#pragma unroll
    for (int q = 0; q < 4; q++)
        oh[q] = __floats2half2_rn(acc[2 * q], acc[2 * q + 1]);
    __stcs(&o4[oi], outv);
    (void)oi2;
}

// ---------------- fused GEMM over all 4 terms: out(b,o,v) = sum_{r,i} xs[r][v][b*128+i] * W[r][i][o] + bias[o]
__device__ __forceinline__ unsigned f2tf(float f) {
    unsigned u;
    asm("cvt.rna.tf32.f32 %0, %1;" : "=r"(u) : "f"(f));
    return u;
}

#define MMA_TF32(C, A, Bf)                                                                  \
    asm volatile("mma.sync.aligned.m16n8k8.row.col.f32.tf32.tf32.f32 "                     \
                 "{%0,%1,%2,%3},{%4,%5,%6,%7},{%8,%9},{%0,%1,%2,%3};"                       \
                 : "+f"((C)[0]), "+f"((C)[1]), "+f"((C)[2]), "+f"((C)[3])                   \
                 : "r"((A)[0]), "r"((A)[1]), "r"((A)[2]), "r"((A)[3]),                      \
                   "r"((Bf)[0]), "r"((Bf)[1]))

// block tile: M=64 (v), N=128 (o), K=512 in chunks of 32. 256 threads = 8 warps (2 x 4).
__global__ void __launch_bounds__(256) gemm_kernel(const float* __restrict__ weight,
                                                   const float* __restrict__ bias,
                                                   float* __restrict__ out) {
    __shared__ unsigned smem[8320];                 // 33.3 KB pool
    unsigned* As = smem;                            // [64][36]  (2304)
    unsigned* Ws = smem + 2304;                     // [32][132] (4224)
    float*    Cs = reinterpret_cast<float*>(smem);  // [128][65] (aliased after compute)

    int tid  = threadIdx.x;
    int lane = tid & 31;
    int warp = tid >> 5;
    int wm   = warp & 1;   // 0..1 : 32 v-rows each
    int wn   = warp >> 1;  // 0..3 : 32 o-cols each
    int bb   = blockIdx.y;
    int v0   = blockIdx.x * 64;

    float c[2][4][4];
#pragma unroll
    for (int nt = 0; nt < 4; nt++) {
        int o = wn * 32 + nt * 8 + (lane & 3) * 2;
        float b0 = bias[o], b1 = bias[o + 1];
#pragma unroll
        for (int mt = 0; mt < 2; mt++) {
            c[mt][nt][0] = b0; c[mt][nt][1] = b1;
            c[mt][nt][2] = b0; c[mt][nt][3] = b1;
        }
    }

    for (int k0 = 0; k0 < 512; k0 += 32) {
        int r  = k0 >> 7;
        int i0 = k0 & 127;
        // load A tile: 64 rows x 32 halves (64B contiguous per row), convert to tf32
        {
            int rowh = tid >> 3;
            int c4   = (tid & 7) * 4;
#pragma unroll
            for (int p = 0; p < 2; p++) {
                int row = p * 32 + rowh;
                int v   = v0 + row;
                uint2 hv = make_uint2(0u, 0u);
                if (v < Vn)
                    hv = *reinterpret_cast<const uint2*>(
                        g_xh + (size_t)(r * Vn + v) * Fn + bb * 128 + i0 + c4);
                __half2 h0 = *reinterpret_cast<__half2*>(&hv.x);
                __half2 h1 = *reinterpret_cast<__half2*>(&hv.y);
                float2 f0 = __half22float2(h0);
                float2 f1 = __half22float2(h1);
                unsigned* dst = As + row * 36 + c4;
                dst[0] = f2tf(f0.x); dst[1] = f2tf(f0.y);
                dst[2] = f2tf(f1.x); dst[3] = f2tf(f1.y);
            }
        }
        // load W tile: 32 x 128 (weight is already (512,128) row-major = (R,Cin,Cout))
        {
#pragma unroll
            for (int idx = tid; idx < 1024; idx += 256) {
                int kk = idx >> 5;
                int oc = (idx & 31) * 4;
                float4 w = *reinterpret_cast<const float4*>(
                    weight + (size_t)(k0 + kk) * 128 + oc);
                unsigned* dst = Ws + kk * 132 + oc;
                dst[0] = f2tf(w.x); dst[1] = f2tf(w.y);
                dst[2] = f2tf(w.z); dst[3] = f2tf(w.w);
            }
        }
        __syncthreads();

#pragma unroll
        for (int k8 = 0; k8 < 32; k8 += 8) {
            unsigned a[2][4];
            int kq = k8 + (lane & 3);
#pragma unroll
            for (int mt = 0; mt < 2; mt++) {
                int arow = wm * 32 + mt * 16 + (lane >> 2);
                a[mt][0] = As[arow * 36 + kq];
                a[mt][1] = As[(arow + 8) * 36 + kq];
                a[mt][2] = As[arow * 36 + kq + 4];
                a[mt][3] = As[(arow + 8) * 36 + kq + 4];
            }
            unsigned bf[4][2];
#pragma unroll
            for (int nt = 0; nt < 4; nt++) {
                int o = wn * 32 + nt * 8 + (lane >> 2);
                bf[nt][0] = Ws[kq * 132 + o];
                bf[nt][1] = Ws[(kq + 4) * 132 + o];
            }
#pragma unroll
            for (int mt = 0; mt < 2; mt++)
#pragma unroll
                for (int nt = 0; nt < 4; nt++)
                    MMA_TF32(c[mt][nt], a[mt], bf[nt]);
        }
        __syncthreads();
    }

    // stage C into shared as [o][v] for coalesced (B,Cout,V) stores
#pragma unroll
    for (int mt = 0; mt < 2; mt++)
#pragma unroll
        for (int nt = 0; nt < 4; nt++) {
            int vr = wm * 32 + mt * 16 + (lane >> 2);
            int o  = wn * 32 + nt * 8 + (lane & 3) * 2;
            Cs[o * 65 + vr]           = c[mt][nt][0];
            Cs[(o + 1) * 65 + vr]     = c[mt][nt][1];
            Cs[o * 65 + vr + 8]       = c[mt][nt][2];
            Cs[(o + 1) * 65 + vr + 8] = c[mt][nt][3];
        }
    __syncthreads();

    for (int idx = tid; idx < 128 * 64; idx += 256) {
        int o  = idx >> 6;
        int vl = idx & 63;
        int v  = v0 + vl;
        if (v < Vn)
            out[((size_t)bb * 128 + o) * Vn + v] = Cs[o * 65 + vl];
    }
}

// ---------------- launch ----------------
extern "C" void kernel_launch(void* const* d_in, const int* in_sizes, int n_in,
                              void* d_out, int out_size) {
    const float* x        = (const float*)d_in[0];
    const float* weight   = (const float*)d_in[1];
    const float* bias     = (const float*)d_in[2];
    const float* lap_vals = (const float*)d_in[3];
    const int*   lap_rows = (const int*)d_in[4];
    const int*   lap_cols = (const int*)d_in[5];
    float* out = (float*)d_out;

    // CSR build
    zero_kernel<<<(Vn + 255) / 256, 256>>>();
    count_kernel<<<NNZn / 256, 256>>>(lap_rows);
    scan_kernel<<<1, 1024>>>();
    scatter_kernel<<<NNZn / 256, 256>>>(lap_rows, lap_cols, lap_vals);

    // x0 = transpose(x) into g_xh[0] (fp16)
    transpose_kernel<<<dim3(Vn / 32, Fn / 32), dim3(32, 32)>>>(x);

    // Chebyshev recursion: x1 = L x0 ; x2 = 2 L x1 - x0 ; x3 = 2 L x2 - x1
    spmm_kernel<0><<<dim3(Vn, 2), 128>>>(0, 0, 1);
    spmm_kernel<1><<<dim3(Vn, 2), 128>>>(1, 0, 2);
    spmm_kernel<1><<<dim3(Vn, 2), 128>>>(2, 1, 3);

    // fused GEMM over all 4 terms + bias, writes (B, Cout, V)
    gemm_kernel<<<dim3((Vn + 63) / 64, Bn), 256>>>(weight, bias, out);
}

// round 3
// speedup vs baseline: 1.5858x; 1.2455x over previous
#include <cuda_runtime.h>
#include <cuda_fp16.h>
#include <cstdint>

#define Vn   20000
#define NNZn 640000
#define Bn   16
#define CINn 128
#define COUTn 128
#define Rn   4
#define Fn   2048   // Bn * CINn

// ---------------- scratch (static device memory; no allocation at runtime) ----------------
__device__ __half g_xh[(size_t)Rn * Vn * Fn];   // 4 Chebyshev terms, each (V, 2048) fp16 (~327 MB)
__device__ __half g_wt[(size_t)COUTn * 512];    // weight transposed: [o][r*128+i] fp16
__device__ int    g_rowptr[Vn + 1];
__device__ int    g_cnt[Vn];
__device__ int    g_fill[Vn];
__device__ int    g_cols[NNZn];                 // pre-scaled: col * 256 (uint4 row index)
__device__ float  g_vals[NNZn];

// ---------------- CSR build ----------------
__global__ void zero_kernel() {
    int i = blockIdx.x * blockDim.x + threadIdx.x;
    if (i < Vn) { g_cnt[i] = 0; g_fill[i] = 0; }
}

__global__ void count_kernel(const int* __restrict__ rows) {
    int j = blockIdx.x * blockDim.x + threadIdx.x;
    if (j < NNZn) atomicAdd(&g_cnt[rows[j]], 1);
}

// single-block exclusive scan over 20000 counters
__global__ void scan_kernel() {
    __shared__ int s[1024];
    int tid = threadIdx.x;
    int carry = 0;
    for (int base = 0; base < Vn; base += 1024) {
        int i = base + tid;
        int v = (i < Vn) ? g_cnt[i] : 0;
        s[tid] = v;
        __syncthreads();
        for (int off = 1; off < 1024; off <<= 1) {
            int t = (tid >= off) ? s[tid - off] : 0;
            __syncthreads();
            s[tid] += t;
            __syncthreads();
        }
        if (i < Vn) g_rowptr[i] = carry + s[tid] - v;
        carry += s[1023];
        __syncthreads();
    }
    if (tid == 0) g_rowptr[Vn] = carry;
}

__global__ void scatter_kernel(const int* __restrict__ rows,
                               const int* __restrict__ cols,
                               const float* __restrict__ vals) {
    int j = blockIdx.x * blockDim.x + threadIdx.x;
    if (j < NNZn) {
        int r = rows[j];
        int p = g_rowptr[r] + atomicAdd(&g_fill[r], 1);
        g_cols[p] = cols[j] << 8;      // scale to uint4-row index (256 uint4 per 2048-half row)
        g_vals[p] = vals[j];
    }
}

// ---------------- weight prep: (R*Cin, Cout) fp32 -> [o][k] fp16 ----------------
__global__ void wprep_kernel(const float* __restrict__ weight) {
    int idx = blockIdx.x * blockDim.x + threadIdx.x;   // 65536 total
    int o = idx >> 9;
    int k = idx & 511;
    g_wt[(size_t)o * 512 + k] = __float2half_rn(weight[(size_t)k * 128 + o]);
}

// ---------------- transpose x (B,Cin,V) -> x0 (V, 2048) fp16 ----------------
__global__ void transpose_kernel(const float* __restrict__ x) {
    __shared__ float tile[32][33];
    int v0 = blockIdx.x * 32;
    int c0 = blockIdx.y * 32;
    int tx = threadIdx.x, ty = threadIdx.y;
    tile[ty][tx] = x[(size_t)(c0 + ty) * Vn + (v0 + tx)];
    __syncthreads();
    g_xh[(size_t)(v0 + ty) * Fn + (c0 + tx)] = __float2half_rn(tile[tx][ty]);
}

// ---------------- SpMM (CSR gather), fp16 rows, feature-halved for L2 residency ----------------
__device__ __forceinline__ void acc8(float* acc, const uint4& r, float w) {
    const __half2* h = reinterpret_cast<const __half2*>(&r);
#pragma unroll
    for (int q = 0; q < 4; q++) {
        float2 a = __half22float2(h[q]);
        acc[2 * q]     = fmaf(w, a.x, acc[2 * q]);
        acc[2 * q + 1] = fmaf(w, a.y, acc[2 * q + 1]);
    }
}

// grid: (Vn, 2), block: 128 threads, each thread one uint4 = 8 halves
template <int MODE>  // 0: xk = L*y ; 1: xk = 2*L*y - xm2
__global__ void __launch_bounds__(128) spmm_kernel(int iy, int im2, int io) {
    const size_t term = (size_t)Vn * 256;   // uint4 per term
    const uint4* __restrict__ y4 = reinterpret_cast<const uint4*>(g_xh) + (size_t)iy  * term;
    const uint4* __restrict__ m4 = reinterpret_cast<const uint4*>(g_xh) + (size_t)im2 * term;
    uint4* __restrict__       o4 = reinterpret_cast<uint4*>(g_xh) + (size_t)io * term;

    int v = blockIdx.x;
    int f = blockIdx.y * 128 + threadIdx.x;   // uint4 index 0..255 within the row
    int s = g_rowptr[v], e = g_rowptr[v + 1];

    float acc[8];
#pragma unroll
    for (int q = 0; q < 8; q++) acc[q] = 0.f;

    int j = s;
    for (; j + 3 < e; j += 4) {
        float w0 = __ldg(&g_vals[j]);     int c0 = __ldg(&g_cols[j]);
        float w1 = __ldg(&g_vals[j + 1]); int c1 = __ldg(&g_cols[j + 1]);
        float w2 = __ldg(&g_vals[j + 2]); int c2 = __ldg(&g_cols[j + 2]);
        float w3 = __ldg(&g_vals[j + 3]); int c3 = __ldg(&g_cols[j + 3]);
        uint4 r0 = __ldg(&y4[(size_t)c0 + f]);
        uint4 r1 = __ldg(&y4[(size_t)c1 + f]);
        uint4 r2 = __ldg(&y4[(size_t)c2 + f]);
        uint4 r3 = __ldg(&y4[(size_t)c3 + f]);
        acc8(acc, r0, w0);
        acc8(acc, r1, w1);
        acc8(acc, r2, w2);
        acc8(acc, r3, w3);
    }
    for (; j < e; j++) {
        float w0 = __ldg(&g_vals[j]); int c0 = __ldg(&g_cols[j]);
        uint4 r0 = __ldg(&y4[(size_t)c0 + f]);
        acc8(acc, r0, w0);
    }

    size_t oi = (size_t)v * 256 + f;
    if (MODE == 1) {
        uint4 mraw = __ldcs(&m4[oi]);
        const __half2* mh = reinterpret_cast<const __half2*>(&mraw);
#pragma unroll
        for (int q = 0; q < 4; q++) {
            float2 m = __half22float2(mh[q]);
            acc[2 * q]     = 2.f * acc[2 * q]     - m.x;
            acc[2 * q + 1] = 2.f * acc[2 * q + 1] - m.y;
        }
    }
    uint4 outv;
    __half2* oh = reinterpret_cast<__half2*>(&outv);
#pragma unroll
    for (int q = 0; q < 4; q++)
        oh[q] = __floats2half2_rn(acc[2 * q], acc[2 * q + 1]);
    __stcs(&o4[oi], outv);
}

// ---------------- fused fp16 GEMM over all 4 terms ----------------
// out(b,o,v) = sum_{r,i} xs[r][v][b*128+i] * W[r][i][o] + bias[o]
#define MMA_F16(C, A, Bf)                                                                   \
    asm volatile("mma.sync.aligned.m16n8k16.row.col.f32.f16.f16.f32 "                      \
                 "{%0,%1,%2,%3},{%4,%5,%6,%7},{%8,%9},{%0,%1,%2,%3};"                       \
                 : "+f"((C)[0]), "+f"((C)[1]), "+f"((C)[2]), "+f"((C)[3])                   \
                 : "r"((A)[0]), "r"((A)[1]), "r"((A)[2]), "r"((A)[3]),                      \
                   "r"((Bf)[0]), "r"((Bf)[1]))

// block tile: M=64 (v), N=128 (o), K=512 in chunks of 64 halves. 256 threads = 8 warps (2 x 4).
__global__ void __launch_bounds__(256) gemm_kernel(const float* __restrict__ bias,
                                                   float* __restrict__ out) {
    __shared__ float smem_pool[8320];                        // 33.3 KB
    unsigned* As = reinterpret_cast<unsigned*>(smem_pool);   // [64][34]  u32 (2 halves each)
    unsigned* Ws = reinterpret_cast<unsigned*>(smem_pool) + 2176; // [128][34]
    float*    Cs = smem_pool;                                // [128][65] (aliased after compute)

    int tid  = threadIdx.x;
    int lane = tid & 31;
    int warp = tid >> 5;
    int wm   = warp & 1;   // 0..1 : 32 v-rows each
    int wn   = warp >> 1;  // 0..3 : 32 o-cols each
    int bb   = blockIdx.y;
    int v0   = blockIdx.x * 64;
    int t    = lane & 3;
    int g    = lane >> 2;

    float c[2][4][4];
#pragma unroll
    for (int nt = 0; nt < 4; nt++) {
        int o = wn * 32 + nt * 8 + t * 2;
        float b0 = bias[o], b1 = bias[o + 1];
#pragma unroll
        for (int mt = 0; mt < 2; mt++) {
            c[mt][nt][0] = b0; c[mt][nt][1] = b1;
            c[mt][nt][2] = b0; c[mt][nt][3] = b1;
        }
    }

    for (int k0 = 0; k0 < 512; k0 += 64) {
        int r  = k0 >> 7;
        int i0 = k0 & 127;
        // A tile: 64 rows x 64 halves (fp16, straight copy)
        {
#pragma unroll
            for (int idx = tid; idx < 512; idx += 256) {
                int row = idx >> 3;
                int seg = idx & 7;
                int v   = v0 + row;
                uint4 hv = make_uint4(0u, 0u, 0u, 0u);
                if (v < Vn)
                    hv = *reinterpret_cast<const uint4*>(
                        g_xh + (size_t)(r * Vn + v) * Fn + bb * 128 + i0 + seg * 8);
                unsigned* dst = As + row * 34 + seg * 4;
                dst[0] = hv.x; dst[1] = hv.y; dst[2] = hv.z; dst[3] = hv.w;
            }
        }
        // W tile: 128 o x 64 k halves from pre-transposed g_wt
        {
#pragma unroll
            for (int idx = tid; idx < 1024; idx += 256) {
                int o   = idx >> 3;
                int seg = idx & 7;
                uint4 w = *reinterpret_cast<const uint4*>(g_wt + (size_t)o * 512 + k0 + seg * 8);
                unsigned* dst = Ws + o * 34 + seg * 4;
                dst[0] = w.x; dst[1] = w.y; dst[2] = w.z; dst[3] = w.w;
            }
        }
        __syncthreads();

#pragma unroll
        for (int s = 0; s < 4; s++) {           // 4 k-steps of 16 halves
            unsigned a[2][4];
#pragma unroll
            for (int mt = 0; mt < 2; mt++) {
                int arow = wm * 32 + mt * 16 + g;
                a[mt][0] = As[arow * 34 + s * 8 + t];
                a[mt][1] = As[(arow + 8) * 34 + s * 8 + t];
                a[mt][2] = As[arow * 34 + s * 8 + t + 4];
                a[mt][3] = As[(arow + 8) * 34 + s * 8 + t + 4];
            }
            unsigned bf[4][2];
#pragma unroll
            for (int nt = 0; nt < 4; nt++) {
                int o = wn * 32 + nt * 8 + g;
                bf[nt][0] = Ws[o * 34 + s * 8 + t];
                bf[nt][1] = Ws[o * 34 + s * 8 + t + 4];
            }
#pragma unroll
            for (int mt = 0; mt < 2; mt++)
#pragma unroll
                for (int nt = 0; nt < 4; nt++)
                    MMA_F16(c[mt][nt], a[mt], bf[nt]);
        }
        __syncthreads();
    }

    // stage C into shared as [o][v] for coalesced (B,Cout,V) stores
#pragma unroll
    for (int mt = 0; mt < 2; mt++)
#pragma unroll
        for (int nt = 0; nt < 4; nt++) {
            int vr = wm * 32 + mt * 16 + g;
            int o  = wn * 32 + nt * 8 + t * 2;
            Cs[o * 65 + vr]           = c[mt][nt][0];
            Cs[(o + 1) * 65 + vr]     = c[mt][nt][1];
            Cs[o * 65 + vr + 8]       = c[mt][nt][2];
            Cs[(o + 1) * 65 + vr + 8] = c[mt][nt][3];
        }
    __syncthreads();

    for (int idx = tid; idx < 128 * 64; idx += 256) {
        int o  = idx >> 6;
        int vl = idx & 63;
        int v  = v0 + vl;
        if (v < Vn)
            out[((size_t)bb * 128 + o) * Vn + v] = Cs[o * 65 + vl];
    }
}

// ---------------- launch ----------------
extern "C" void kernel_launch(void* const* d_in, const int* in_sizes, int n_in,
                              void* d_out, int out_size) {
    const float* x        = (const float*)d_in[0];
    const float* weight   = (const float*)d_in[1];
    const float* bias     = (const float*)d_in[2];
    const float* lap_vals = (const float*)d_in[3];
    const int*   lap_rows = (const int*)d_in[4];
    const int*   lap_cols = (const int*)d_in[5];
    float* out = (float*)d_out;

    // CSR build + weight prep
    zero_kernel<<<(Vn + 255) / 256, 256>>>();
    count_kernel<<<NNZn / 256, 256>>>(lap_rows);
    scan_kernel<<<1, 1024>>>();
    scatter_kernel<<<NNZn / 256, 256>>>(lap_rows, lap_cols, lap_vals);
    wprep_kernel<<<256, 256>>>(weight);

    // x0 = transpose(x) into g_xh[0] (fp16)
    transpose_kernel<<<dim3(Vn / 32, Fn / 32), dim3(32, 32)>>>(x);

    // Chebyshev recursion: x1 = L x0 ; x2 = 2 L x1 - x0 ; x3 = 2 L x2 - x1
    spmm_kernel<0><<<dim3(Vn, 2), 128>>>(0, 0, 1);
    spmm_kernel<1><<<dim3(Vn, 2), 128>>>(1, 0, 2);
    spmm_kernel<1><<<dim3(Vn, 2), 128>>>(2, 1, 3);

    // fused fp16 GEMM over all 4 terms + bias, writes (B, Cout, V)
    gemm_kernel<<<dim3((Vn + 63) / 64, Bn), 256>>>(bias, out);
}

// round 4
// speedup vs baseline: 1.8566x; 1.1707x over previous
#include <cuda_runtime.h>
#include <cuda_fp16.h>
#include <cstdint>

#define Vn   20000
#define NNZn 640000
#define Bn   16
#define CINn 128
#define COUTn 128
#define Rn   4
#define Fn   2048   // Bn * CINn

// ---------------- scratch (static device memory; no allocation at runtime) ----------------
__device__ __half g_xh[(size_t)Rn * Vn * Fn];   // 4 Chebyshev terms, each (V, 2048) fp16 (~327 MB)
__device__ __half g_wt[(size_t)COUTn * 512];    // weight transposed: [o][r*128+i] fp16
__device__ int    g_rowptr[Vn + 1];
__device__ int    g_cnt[Vn];
__device__ int    g_fill[Vn];
__device__ int2   g_ev[NNZn];                   // packed: {col*256 (uint4 row idx), val bits}

// ---------------- CSR zero ----------------
__global__ void zero_kernel() {
    int i = blockIdx.x * blockDim.x + threadIdx.x;
    if (i < Vn) { g_cnt[i] = 0; g_fill[i] = 0; }
}

// ---------------- fused prelude: count | transpose | wprep (independent work) ----------------
#define COUNT_BLKS 2500
#define TRANS_BLKS 40000     // (Vn/32) * (Fn/32) = 625 * 64
#define WPREP_BLKS 256
__global__ void __launch_bounds__(256) fused_prelude_kernel(const int* __restrict__ rows,
                                                            const float* __restrict__ x,
                                                            const float* __restrict__ weight) {
    __shared__ float tile[32][33];
    int bid = blockIdx.x;
    int tid = threadIdx.x;
    if (bid < COUNT_BLKS) {
        int j = bid * 256 + tid;
        if (j < NNZn) atomicAdd(&g_cnt[rows[j]], 1);
    } else if (bid < COUNT_BLKS + TRANS_BLKS) {
        int b2 = bid - COUNT_BLKS;
        int v0 = (b2 % 625) * 32;
        int c0 = (b2 / 625) * 32;
        int tx = tid & 31;
        int ty0 = tid >> 5;          // 0..7
#pragma unroll
        for (int q = 0; q < 4; q++) {
            int ty = ty0 + q * 8;
            tile[ty][tx] = x[(size_t)(c0 + ty) * Vn + (v0 + tx)];
        }
        __syncthreads();
#pragma unroll
        for (int q = 0; q < 4; q++) {
            int ty = ty0 + q * 8;
            g_xh[(size_t)(v0 + ty) * Fn + (c0 + tx)] = __float2half_rn(tile[tx][ty]);
        }
    } else {
        int idx = (bid - COUNT_BLKS - TRANS_BLKS) * 256 + tid;   // 65536 total
        int o = idx >> 9;
        int k = idx & 511;
        g_wt[(size_t)o * 512 + k] = __float2half_rn(weight[(size_t)k * 128 + o]);
    }
}

// single-block exclusive scan over 20000 counters
__global__ void scan_kernel() {
    __shared__ int s[1024];
    int tid = threadIdx.x;
    int carry = 0;
    for (int base = 0; base < Vn; base += 1024) {
        int i = base + tid;
        int v = (i < Vn) ? g_cnt[i] : 0;
        s[tid] = v;
        __syncthreads();
        for (int off = 1; off < 1024; off <<= 1) {
            int t = (tid >= off) ? s[tid - off] : 0;
            __syncthreads();
            s[tid] += t;
            __syncthreads();
        }
        if (i < Vn) g_rowptr[i] = carry + s[tid] - v;
        carry += s[1023];
        __syncthreads();
    }
    if (tid == 0) g_rowptr[Vn] = carry;
}

__global__ void scatter_kernel(const int* __restrict__ rows,
                               const int* __restrict__ cols,
                               const float* __restrict__ vals) {
    int j = blockIdx.x * blockDim.x + threadIdx.x;
    if (j < NNZn) {
        int r = rows[j];
        int p = g_rowptr[r] + atomicAdd(&g_fill[r], 1);
        g_ev[p] = make_int2(cols[j] << 8, __float_as_int(vals[j]));
    }
}

// ---------------- SpMM (CSR gather), fp16 rows, feature-halved for L2 residency ----------------
__device__ __forceinline__ void acc8(float* acc, const uint4& r, float w) {
    const __half2* h = reinterpret_cast<const __half2*>(&r);
#pragma unroll
    for (int q = 0; q < 4; q++) {
        float2 a = __half22float2(h[q]);
        acc[2 * q]     = fmaf(w, a.x, acc[2 * q]);
        acc[2 * q + 1] = fmaf(w, a.y, acc[2 * q + 1]);
    }
}

// grid: (Vn, 2), block: 128 threads, each thread one uint4 = 8 halves
template <int MODE>  // 0: xk = L*y ; 1: xk = 2*L*y - xm2
__global__ void __launch_bounds__(128) spmm_kernel(int iy, int im2, int io) {
    const size_t term = (size_t)Vn * 256;   // uint4 per term
    const uint4* __restrict__ y4 = reinterpret_cast<const uint4*>(g_xh) + (size_t)iy  * term;
    const uint4* __restrict__ m4 = reinterpret_cast<const uint4*>(g_xh) + (size_t)im2 * term;
    uint4* __restrict__       o4 = reinterpret_cast<uint4*>(g_xh) + (size_t)io * term;

    int v = blockIdx.x;
    int f = blockIdx.y * 128 + threadIdx.x;   // uint4 index 0..255 within the row
    int s = g_rowptr[v], e = g_rowptr[v + 1];

    float acc[8];
#pragma unroll
    for (int q = 0; q < 8; q++) acc[q] = 0.f;

    int j = s;
    for (; j + 7 < e; j += 8) {
        int2 ev0 = __ldg(&g_ev[j]);
        int2 ev1 = __ldg(&g_ev[j + 1]);
        int2 ev2 = __ldg(&g_ev[j + 2]);
        int2 ev3 = __ldg(&g_ev[j + 3]);
        int2 ev4 = __ldg(&g_ev[j + 4]);
        int2 ev5 = __ldg(&g_ev[j + 5]);
        int2 ev6 = __ldg(&g_ev[j + 6]);
        int2 ev7 = __ldg(&g_ev[j + 7]);
        uint4 r0 = __ldg(&y4[(size_t)ev0.x + f]);
        uint4 r1 = __ldg(&y4[(size_t)ev1.x + f]);
        uint4 r2 = __ldg(&y4[(size_t)ev2.x + f]);
        uint4 r3 = __ldg(&y4[(size_t)ev3.x + f]);
        uint4 r4 = __ldg(&y4[(size_t)ev4.x + f]);
        uint4 r5 = __ldg(&y4[(size_t)ev5.x + f]);
        uint4 r6 = __ldg(&y4[(size_t)ev6.x + f]);
        uint4 r7 = __ldg(&y4[(size_t)ev7.x + f]);
        acc8(acc, r0, __int_as_float(ev0.y));
        acc8(acc, r1, __int_as_float(ev1.y));
        acc8(acc, r2, __int_as_float(ev2.y));
        acc8(acc, r3, __int_as_float(ev3.y));
        acc8(acc, r4, __int_as_float(ev4.y));
        acc8(acc, r5, __int_as_float(ev5.y));
        acc8(acc, r6, __int_as_float(ev6.y));
        acc8(acc, r7, __int_as_float(ev7.y));
    }
    for (; j < e; j++) {
        int2 ev = __ldg(&g_ev[j]);
        uint4 r0 = __ldg(&y4[(size_t)ev.x + f]);
        acc8(acc, r0, __int_as_float(ev.y));
    }

    size_t oi = (size_t)v * 256 + f;
    if (MODE == 1) {
        uint4 mraw = __ldcs(&m4[oi]);
        const __half2* mh = reinterpret_cast<const __half2*>(&mraw);
#pragma unroll
        for (int q = 0; q < 4; q++) {
            float2 m = __half22float2(mh[q]);
            acc[2 * q]     = 2.f * acc[2 * q]     - m.x;
            acc[2 * q + 1] = 2.f * acc[2 * q + 1] - m.y;
        }
    }
    uint4 outv;
    __half2* oh = reinterpret_cast<__half2*>(&outv);
#pragma unroll
    for (int q = 0; q < 4; q++)
        oh[q] = __floats2half2_rn(acc[2 * q], acc[2 * q + 1]);
    __stcs(&o4[oi], outv);
}

// ---------------- fused fp16 GEMM over all 4 terms ----------------
// out(b,o,v) = sum_{r,i} xs[r][v][b*128+i] * W[r][i][o] + bias[o]
#define MMA_F16(C, A, Bf)                                                                   \
    asm volatile("mma.sync.aligned.m16n8k16.row.col.f32.f16.f16.f32 "                      \
                 "{%0,%1,%2,%3},{%4,%5,%6,%7},{%8,%9},{%0,%1,%2,%3};"                       \
                 : "+f"((C)[0]), "+f"((C)[1]), "+f"((C)[2]), "+f"((C)[3])                   \
                 : "r"((A)[0]), "r"((A)[1]), "r"((A)[2]), "r"((A)[3]),                      \
                   "r"((Bf)[0]), "r"((Bf)[1]))

// block tile: M=128 (v), N=128 (o), K=512 in chunks of 64 halves. 256 threads = 8 warps (2 x 4).
// warp wm in {0,1}; warp-m row for m-tile mt: arow = mt*32 + wm*16  (mt = 0..3)
__global__ void __launch_bounds__(256) gemm_kernel(const float* __restrict__ bias,
                                                   float* __restrict__ out) {
    __shared__ float smem_pool[8832];                        // 35.3 KB
    unsigned* As = reinterpret_cast<unsigned*>(smem_pool);        // [128][34] u32
    unsigned* Ws = reinterpret_cast<unsigned*>(smem_pool) + 4352; // [128][34] u32
    float*    Cs = smem_pool;                                     // [128][65] float (aliased)

    int tid  = threadIdx.x;
    int lane = tid & 31;
    int warp = tid >> 5;
    int wm   = warp & 1;
    int wn   = warp >> 1;  // 0..3 : 32 o-cols each
    int bb   = blockIdx.y;
    int v0   = blockIdx.x * 128;
    int t    = lane & 3;
    int g    = lane >> 2;

    float c[4][4][4];
#pragma unroll
    for (int nt = 0; nt < 4; nt++) {
        int o = wn * 32 + nt * 8 + t * 2;
        float b0 = bias[o], b1 = bias[o + 1];
#pragma unroll
        for (int mt = 0; mt < 4; mt++) {
            c[mt][nt][0] = b0; c[mt][nt][1] = b1;
            c[mt][nt][2] = b0; c[mt][nt][3] = b1;
        }
    }

    for (int k0 = 0; k0 < 512; k0 += 64) {
        int r  = k0 >> 7;
        int i0 = k0 & 127;
        // A tile: 128 rows x 64 halves
        {
#pragma unroll
            for (int idx = tid; idx < 1024; idx += 256) {
                int row = idx >> 3;
                int seg = idx & 7;
                int v   = v0 + row;
                uint4 hv = make_uint4(0u, 0u, 0u, 0u);
                if (v < Vn)
                    hv = *reinterpret_cast<const uint4*>(
                        g_xh + (size_t)(r * Vn + v) * Fn + bb * 128 + i0 + seg * 8);
                unsigned* dst = As + row * 34 + seg * 4;
                dst[0] = hv.x; dst[1] = hv.y; dst[2] = hv.z; dst[3] = hv.w;
            }
        }
        // W tile: 128 o x 64 k halves from pre-transposed g_wt
        {
#pragma unroll
            for (int idx = tid; idx < 1024; idx += 256) {
                int o   = idx >> 3;
                int seg = idx & 7;
                uint4 w = *reinterpret_cast<const uint4*>(g_wt + (size_t)o * 512 + k0 + seg * 8);
                unsigned* dst = Ws + o * 34 + seg * 4;
                dst[0] = w.x; dst[1] = w.y; dst[2] = w.z; dst[3] = w.w;
            }
        }
        __syncthreads();

#pragma unroll
        for (int s = 0; s < 4; s++) {           // 4 k-steps of 16 halves
            unsigned bf[4][2];
#pragma unroll
            for (int nt = 0; nt < 4; nt++) {
                int o = wn * 32 + nt * 8 + g;
                bf[nt][0] = Ws[o * 34 + s * 8 + t];
                bf[nt][1] = Ws[o * 34 + s * 8 + t + 4];
            }
#pragma unroll
            for (int mt = 0; mt < 4; mt++) {
                int arow = mt * 32 + wm * 16 + g;
                unsigned a[4];
                a[0] = As[arow * 34 + s * 8 + t];
                a[1] = As[(arow + 8) * 34 + s * 8 + t];
                a[2] = As[arow * 34 + s * 8 + t + 4];
                a[3] = As[(arow + 8) * 34 + s * 8 + t + 4];
#pragma unroll
                for (int nt = 0; nt < 4; nt++)
                    MMA_F16(c[mt][nt], a, bf[nt]);
            }
        }
        __syncthreads();
    }

    // stage C into shared as [o][v] for coalesced (B,Cout,V) stores — two passes of 64 rows
#pragma unroll
    for (int p = 0; p < 2; p++) {
#pragma unroll
        for (int mth = 0; mth < 2; mth++) {
            int mt = 2 * p + mth;
#pragma unroll
            for (int nt = 0; nt < 4; nt++) {
                int vr = mth * 32 + wm * 16 + g;     // 0..63 within pass
                int o  = wn * 32 + nt * 8 + t * 2;
                Cs[o * 65 + vr]           = c[mt][nt][0];
                Cs[(o + 1) * 65 + vr]     = c[mt][nt][1];
                Cs[o * 65 + vr + 8]       = c[mt][nt][2];
                Cs[(o + 1) * 65 + vr + 8] = c[mt][nt][3];
            }
        }
        __syncthreads();
        for (int idx = tid; idx < 128 * 64; idx += 256) {
            int o  = idx >> 6;
            int vl = idx & 63;
            int v  = v0 + p * 64 + vl;
            if (v < Vn)
                out[((size_t)bb * 128 + o) * Vn + v] = Cs[o * 65 + vl];
        }
        __syncthreads();
    }
}

// ---------------- launch ----------------
extern "C" void kernel_launch(void* const* d_in, const int* in_sizes, int n_in,
                              void* d_out, int out_size) {
    const float* x        = (const float*)d_in[0];
    const float* weight   = (const float*)d_in[1];
    const float* bias     = (const float*)d_in[2];
    const float* lap_vals = (const float*)d_in[3];
    const int*   lap_rows = (const int*)d_in[4];
    const int*   lap_cols = (const int*)d_in[5];
    float* out = (float*)d_out;

    // prelude: zero counters, then fused {count | transpose | wprep}, scan, scatter
    zero_kernel<<<(Vn + 255) / 256, 256>>>();
    fused_prelude_kernel<<<COUNT_BLKS + TRANS_BLKS + WPREP_BLKS, 256>>>(lap_rows, x, weight);
    scan_kernel<<<1, 1024>>>();
    scatter_kernel<<<NNZn / 256, 256>>>(lap_rows, lap_cols, lap_vals);

    // Chebyshev recursion: x1 = L x0 ; x2 = 2 L x1 - x0 ; x3 = 2 L x2 - x1
    spmm_kernel<0><<<dim3(Vn, 2), 128>>>(0, 0, 1);
    spmm_kernel<1><<<dim3(Vn, 2), 128>>>(1, 0, 2);
    spmm_kernel<1><<<dim3(Vn, 2), 128>>>(2, 1, 3);

    // fused fp16 GEMM over all 4 terms + bias, writes (B, Cout, V)
    gemm_kernel<<<dim3((Vn + 127) / 128, Bn), 256>>>(bias, out);
}